// round 5
// baseline (speedup 1.0000x reference)
#include <cuda_runtime.h>
#include <cuda_bf16.h>

// UmbralCone: hyperbolic cone distance.
//  weight: f32 [SIZE=100000, 32]   (d_in[0])
//  inputs: i32 [B=16384, 50]       (d_in[1])
//  out:    f32 [B, 49]
//
// Block of 256 threads handles RPB=5 batch rows:
//  Phase 1: preload 250 row indices to registers, gather 250 weight rows
//           (128B each) into DIM-MAJOR SMEM via cp.async (L1-bypass, MLP~16).
//           Dim-major: float4 i of row g lives at s4[i*250+g] -> Phase-2b
//           loads are conflict-free AND use immediate offsets (no swizzle ALU).
//           NOTE: 2000 gathers over 256 threads -> last unrolled iteration
//           (u==7) only valid for g0 < 26. (R4 bug: unguarded overflow into
//           the next dim-slab corrupted parent rows.)
//  Phase 2a: 5 threads compute per-row parent scalars.
//  Phase 2b: one thread per (row, child) pair: dot/norm from SMEM + tail.

#define RPB   5
#define KTOT  50
#define NCH   49
#define NROWS (RPB * KTOT)   // 250

__device__ __forceinline__ float arcosh_fast(float x) {
    x = fmaxf(x, 1.0f + 1e-7f);
    return __logf(x + sqrtf(x * x - 1.0f));
}

__device__ __forceinline__ void cp16(float4* dst_smem, const float4* src_gmem) {
    unsigned dst = (unsigned)__cvta_generic_to_shared(dst_smem);
    asm volatile("cp.async.cg.shared.global [%0], [%1], 16;\n"
                 :: "r"(dst), "l"(src_gmem));
}

__global__ __launch_bounds__(256, 7)
void umbral_cone_kernel(const float* __restrict__ weight,
                        const int* __restrict__ inputs,
                        float* __restrict__ out,
                        int B) {
    // dim-major: s4[i*NROWS + g] = float4 i of gathered row g   (32000 B)
    __shared__ __align__(16) float4 s4[8 * NROWS];
    __shared__ __align__(16) float4 srow[RPB * 2];   // per-row parent scalars

    const int tid  = threadIdx.x;
    const int row0 = blockIdx.x * RPB;
    const int g0   = tid >> 3;      // gathered-row id at u=0  (0..31)
    const int fi   = tid & 7;       // float4 lane within the 128B row
    const long long gbase = (long long)row0 * KTOT;
    const bool full = (row0 + RPB <= B);

    // ---------- Phase 1: index preload + cp.async gather ----------
    if (full) {
        int idxv[8];
        #pragma unroll
        for (int u = 0; u < 8; u++) {
            int g = g0 + 32 * u;                      // 0..255; only <250 valid
            if (u < 7 || g0 < NROWS - 224)            // u==7: g0 < 26
                idxv[u] = inputs[gbase + g];
        }
        #pragma unroll
        for (int u = 0; u < 8; u++) {
            int g = g0 + 32 * u;
            if (u < 7 || g0 < NROWS - 224)
                cp16(&s4[fi * NROWS + g],
                     (const float4*)(weight + (long long)idxv[u] * 32) + fi);
        }
    } else {
        const int lim = (B - row0) * KTOT;
        #pragma unroll
        for (int u = 0; u < 8; u++) {
            int g = g0 + 32 * u;
            if (g < lim && g < NROWS) {
                int idx = inputs[gbase + g];
                cp16(&s4[fi * NROWS + g],
                     (const float4*)(weight + (long long)idx * 32) + fi);
            }
        }
    }
    asm volatile("cp.async.commit_group;\n");
    asm volatile("cp.async.wait_group 0;\n" ::: "memory");
    __syncthreads();

    // ---------- Phase 2a: per-row parent scalars (5 threads) ----------
    if (tid < RPB && (full || tid < B - row0)) {
        const int p0 = tid * KTOT;
        float np2 = 0.f;
        #pragma unroll
        for (int i = 0; i < 8; i++) {
            float4 v = s4[i * NROWS + p0];
            np2 = fmaf(v.x, v.x, fmaf(v.y, v.y, fmaf(v.z, v.z, fmaf(v.w, v.w, np2))));
        }
        const float SINH_R = 0.10016675001984403f;   // sinh(0.1)
        const float COSH_R = 1.0050041680558035f;    // cosh(0.1)
        const float EK     = 1.0100501670841680f;    // exp(0.01)

        float np      = sqrtf(np2);
        float inv_np  = __fdividef(1.0f, np);
        float sin_beta = SINH_R * 0.5f * (1.0f - np2) * inv_np;
        float cos_beta = sqrtf(fmaxf(1.0f - sin_beta * sin_beta, 0.0f));
        float hp = arcosh_fast(COSH_R * __fdividef(1.0f - np2, 1.0f + np2));

        float tmp   = __fdividef(1.0f + np, 1.0f - np);
        float ektmp = EK * tmp;
        float scale = __fdividef(ektmp - 1.0f, (ektmp + 1.0f) * np);
        float nps2  = scale * scale * np2;
        float w2    = __fdividef(2.0f, 1.0f - nps2);

        srow[tid * 2 + 0] = make_float4(inv_np, sin_beta, cos_beta, hp);
        srow[tid * 2 + 1] = make_float4(2.0f * scale, nps2, w2, 0.0f);
    }
    __syncthreads();

    // ---------- Phase 2b: one thread per (row, child) pair ----------
    if (tid < RPB * NCH) {
        const int r = tid / NCH;
        const int j = tid - r * NCH;
        if (full || row0 + r < B) {
            const int p0 = r * KTOT;
            const int c  = p0 + 1 + j;

            float nc2 = 0.f, dot = 0.f;
            #pragma unroll
            for (int i = 0; i < 8; i++) {
                float4 pv = s4[i * NROWS + p0];   // broadcast
                float4 cv = s4[i * NROWS + c];    // consecutive 16B -> no conflict
                nc2 = fmaf(cv.x, cv.x, nc2); nc2 = fmaf(cv.y, cv.y, nc2);
                nc2 = fmaf(cv.z, cv.z, nc2); nc2 = fmaf(cv.w, cv.w, nc2);
                dot = fmaf(pv.x, cv.x, dot); dot = fmaf(pv.y, cv.y, dot);
                dot = fmaf(pv.z, cv.z, dot); dot = fmaf(pv.w, cv.w, dot);
            }

            float4 a = srow[r * 2 + 0];   // inv_np, sin_beta, cos_beta, hp
            float4 b = srow[r * 2 + 1];   // 2*scale, nps2, 2/(1-nps2)

            float inv_nc = rsqrtf(nc2);
            float nc     = nc2 * inv_nc;

            float ca = dot * a.x * inv_nc;
            ca = fminf(fmaxf(ca, -1.0f + 1e-7f), 1.0f - 1e-7f);
            float sa = sqrtf(1.0f - ca * ca);            // sin(alpha)

            float sin_theta = sa * a.z - ca * a.y;       // sin(alpha - beta)
            float temp = 2.0f * nc * sin_theta;

            float omn     = 1.0f - nc2;
            float inv_omn = __fdividef(1.0f, omn);
            float hc = (1.0f + nc2) * rsqrtf(fmaf(omn, omn, temp * temp));
            float altitude = a.w - hc;

            float dist;
            if (altitude > 0.0f) {
                float diff2 = fmaf(-b.x, dot, nc2 + b.y);        // |c - s*p|^2
                float z = fmaf(b.z * diff2, inv_omn, 1.0f);
                dist = arcosh_fast(z);
            } else {
                float x  = temp * inv_omn;
                float ax = fabsf(x);
                float as = __logf(ax + sqrtf(fmaf(ax, ax, 1.0f)));
                dist = copysignf(as, x) + 0.1f;                  // RADIUS
            }

            out[(long long)(row0 + r) * NCH + j] = dist;
        }
    }
}

extern "C" void kernel_launch(void* const* d_in, const int* in_sizes, int n_in,
                              void* d_out, int out_size) {
    const float* weight = (const float*)d_in[0];
    const int*   inputs = (const int*)d_in[1];
    float*       out    = (float*)d_out;

    int B = in_sizes[1] / KTOT;          // 16384
    int grid = (B + RPB - 1) / RPB;      // 3277

    umbral_cone_kernel<<<grid, 256>>>(weight, inputs, out, B);
}

// round 6
// speedup vs baseline: 1.7682x; 1.7682x over previous
#include <cuda_runtime.h>
#include <cuda_bf16.h>

// UmbralCone: hyperbolic cone distance.
//  weight: f32 [SIZE=100000, 32]   (d_in[0])
//  inputs: i32 [B=16384, 50]       (d_in[1])
//  out:    f32 [B, 49]
//
// Block of 256 threads handles RPB=5 batch rows:
//  Phase 1: preload 250 row indices, gather 250 weight rows (128B) into
//           PADDED ROW-MAJOR SMEM (stride 9 float4 = 144B) via cp.async.
//           Stride-36-floats => conflict-free STS.128 AND LDS.128 (per-phase
//           banks 4l+c distinct), with immediate-offset loads (no swizzle ALU).
//           (R5 dim-major had 4-way store conflicts: slab stride 1000 % 32 == 8.)
//  Phase 2a: 5 threads compute per-row parent scalars.
//  Phase 2b: one thread per (row, child) pair: dot/norm from SMEM + tail.

#define RPB   5
#define KTOT  50
#define NCH   49
#define NROWS (RPB * KTOT)   // 250
#define RSTR  9              // float4 stride per row (144B)

__device__ __forceinline__ float arcosh_fast(float x) {
    x = fmaxf(x, 1.0f + 1e-7f);
    return __logf(x + sqrtf(x * x - 1.0f));
}

__device__ __forceinline__ void cp16(float4* dst_smem, const float4* src_gmem) {
    unsigned dst = (unsigned)__cvta_generic_to_shared(dst_smem);
    asm volatile("cp.async.cg.shared.global [%0], [%1], 16;\n"
                 :: "r"(dst), "l"(src_gmem));
}

__global__ __launch_bounds__(256, 6)
void umbral_cone_kernel(const float* __restrict__ weight,
                        const int* __restrict__ inputs,
                        float* __restrict__ out,
                        int B) {
    __shared__ __align__(16) float4 s4[NROWS * RSTR];   // 36000 B
    __shared__ __align__(16) float4 srow[RPB * 2];      // per-row parent scalars

    const int tid  = threadIdx.x;
    const int row0 = blockIdx.x * RPB;
    const int g0   = tid >> 3;      // gathered-row id at u=0  (0..31)
    const int fi   = tid & 7;       // float4 lane within the 128B row
    const long long gbase = (long long)row0 * KTOT;
    const bool full = (row0 + RPB <= B);

    // ---------- Phase 1: index preload + cp.async gather ----------
    if (full) {
        int idxv[8];
        #pragma unroll
        for (int u = 0; u < 8; u++) {
            int g = g0 + 32 * u;                      // 0..255; only <250 valid
            if (u < 7 || g0 < NROWS - 224)            // u==7: g0 < 26
                idxv[u] = inputs[gbase + g];
        }
        #pragma unroll
        for (int u = 0; u < 8; u++) {
            int g = g0 + 32 * u;
            if (u < 7 || g0 < NROWS - 224)
                cp16(&s4[g * RSTR + fi],
                     (const float4*)(weight + (long long)idxv[u] * 32) + fi);
        }
    } else {
        const int lim = (B - row0) * KTOT;
        #pragma unroll
        for (int u = 0; u < 8; u++) {
            int g = g0 + 32 * u;
            if (g < lim && g < NROWS) {
                int idx = inputs[gbase + g];
                cp16(&s4[g * RSTR + fi],
                     (const float4*)(weight + (long long)idx * 32) + fi);
            }
        }
    }
    asm volatile("cp.async.commit_group;\n");
    asm volatile("cp.async.wait_group 0;\n" ::: "memory");
    __syncthreads();

    // ---------- Phase 2a: per-row parent scalars (5 threads) ----------
    if (tid < RPB && (full || tid < B - row0)) {
        const float4* pb = &s4[(tid * KTOT) * RSTR];
        float np2 = 0.f;
        #pragma unroll
        for (int i = 0; i < 8; i++) {
            float4 v = pb[i];
            np2 = fmaf(v.x, v.x, fmaf(v.y, v.y, fmaf(v.z, v.z, fmaf(v.w, v.w, np2))));
        }
        const float SINH_R = 0.10016675001984403f;   // sinh(0.1)
        const float COSH_R = 1.0050041680558035f;    // cosh(0.1)
        const float EK     = 1.0100501670841680f;    // exp(0.01)

        float np      = sqrtf(np2);
        float inv_np  = __fdividef(1.0f, np);
        float sin_beta = SINH_R * 0.5f * (1.0f - np2) * inv_np;
        float cos_beta = sqrtf(fmaxf(1.0f - sin_beta * sin_beta, 0.0f));
        float hp = arcosh_fast(COSH_R * __fdividef(1.0f - np2, 1.0f + np2));

        float tmp   = __fdividef(1.0f + np, 1.0f - np);
        float ektmp = EK * tmp;
        float scale = __fdividef(ektmp - 1.0f, (ektmp + 1.0f) * np);
        float nps2  = scale * scale * np2;
        float w2    = __fdividef(2.0f, 1.0f - nps2);

        srow[tid * 2 + 0] = make_float4(inv_np, sin_beta, cos_beta, hp);
        srow[tid * 2 + 1] = make_float4(2.0f * scale, nps2, w2, 0.0f);
    }
    __syncthreads();

    // ---------- Phase 2b: one thread per (row, child) pair ----------
    if (tid < RPB * NCH) {
        const int r = tid / NCH;
        const int j = tid - r * NCH;
        if (full || row0 + r < B) {
            const float4* pb = &s4[(r * KTOT) * RSTR];
            const float4* cb = &s4[(r * KTOT + 1 + j) * RSTR];

            float nc2 = 0.f, dot = 0.f;
            #pragma unroll
            for (int i = 0; i < 8; i++) {
                float4 pv = pb[i];   // broadcast within phase
                float4 cv = cb[i];   // stride-36 floats -> conflict-free phase
                nc2 = fmaf(cv.x, cv.x, nc2); nc2 = fmaf(cv.y, cv.y, nc2);
                nc2 = fmaf(cv.z, cv.z, nc2); nc2 = fmaf(cv.w, cv.w, nc2);
                dot = fmaf(pv.x, cv.x, dot); dot = fmaf(pv.y, cv.y, dot);
                dot = fmaf(pv.z, cv.z, dot); dot = fmaf(pv.w, cv.w, dot);
            }

            float4 a = srow[r * 2 + 0];   // inv_np, sin_beta, cos_beta, hp
            float4 b = srow[r * 2 + 1];   // 2*scale, nps2, 2/(1-nps2)

            float inv_nc = rsqrtf(nc2);
            float nc     = nc2 * inv_nc;

            float ca = dot * a.x * inv_nc;
            ca = fminf(fmaxf(ca, -1.0f + 1e-7f), 1.0f - 1e-7f);
            float sa = sqrtf(1.0f - ca * ca);            // sin(alpha)

            float sin_theta = sa * a.z - ca * a.y;       // sin(alpha - beta)
            float temp = 2.0f * nc * sin_theta;

            float omn     = 1.0f - nc2;
            float inv_omn = __fdividef(1.0f, omn);
            float hc = (1.0f + nc2) * rsqrtf(fmaf(omn, omn, temp * temp));
            float altitude = a.w - hc;

            float dist;
            if (altitude > 0.0f) {
                float diff2 = fmaf(-b.x, dot, nc2 + b.y);        // |c - s*p|^2
                float z = fmaf(b.z * diff2, inv_omn, 1.0f);
                dist = arcosh_fast(z);
            } else {
                float x  = temp * inv_omn;
                float ax = fabsf(x);
                float as = __logf(ax + sqrtf(fmaf(ax, ax, 1.0f)));
                dist = copysignf(as, x) + 0.1f;                  // RADIUS
            }

            out[(long long)(row0 + r) * NCH + j] = dist;
        }
    }
}

extern "C" void kernel_launch(void* const* d_in, const int* in_sizes, int n_in,
                              void* d_out, int out_size) {
    const float* weight = (const float*)d_in[0];
    const int*   inputs = (const int*)d_in[1];
    float*       out    = (float*)d_out;

    int B = in_sizes[1] / KTOT;          // 16384
    int grid = (B + RPB - 1) / RPB;      // 3277

    umbral_cone_kernel<<<grid, 256>>>(weight, inputs, out, B);
}